// round 8
// baseline (speedup 1.0000x reference)
#include <cuda_runtime.h>
#include <cstdint>

#define P_DIM 1024
#define Q_DIM 1024
#define S_DIM 128
#define B_DIM 8

#define TP 32    // p-tile
#define TQ 32    // q-tile
#define SPH 64   // s-values per phase (2 phases)
#define NTHR 128

// Transposed projections + rank-1 vectors (device-global scratch)
__device__ __align__(16) float g_pr_t[S_DIM][P_DIM];  // (product @ w1[:S])^T
__device__ __align__(16) float g_pe_t[S_DIM][Q_DIM];  // (person  @ w1[S:])^T
__device__ __align__(16) float g_a[P_DIM];  // sum_s pr*w2 + 2*ln2*sum(w2)
__device__ __align__(16) float g_b[Q_DIM];  // sum_s pe*w2

// ---------------- packed f32x2 helpers (sm_100a) ----------------
__device__ __forceinline__ uint64_t fdup(float f) {
  uint64_t r;
  asm("mov.b64 %0, {%1, %1};" : "=l"(r) : "r"(__float_as_uint(f)));
  return r;
}
__device__ __forceinline__ uint64_t addx2(uint64_t a, uint64_t b) {
  uint64_t d; asm("add.rn.f32x2 %0, %1, %2;" : "=l"(d) : "l"(a), "l"(b)); return d;
}
__device__ __forceinline__ uint64_t mulx2(uint64_t a, uint64_t b) {
  uint64_t d; asm("mul.rn.f32x2 %0, %1, %2;" : "=l"(d) : "l"(a), "l"(b)); return d;
}
__device__ __forceinline__ uint64_t fmax2(uint64_t a, uint64_t b, uint64_t c) {
  uint64_t d; asm("fma.rn.f32x2 %0, %1, %2, %3;" : "=l"(d) : "l"(a), "l"(b), "l"(c)); return d;
}
__device__ __forceinline__ float2 unpk(uint64_t v) {
  uint32_t lo, hi;
  asm("mov.b64 {%0, %1}, %2;" : "=r"(lo), "=r"(hi) : "l"(v));
  return make_float2(__uint_as_float(lo), __uint_as_float(hi));
}
__device__ __forceinline__ uint64_t pk(float lo, float hi) {
  uint64_t r;
  asm("mov.b64 %0, {%1, %2};" : "=l"(r) : "r"(__float_as_uint(lo)), "r"(__float_as_uint(hi)));
  return r;
}

// ---------------------------------------------------------------------------
// Prologue: blocked projection (8 rows per CTA) + rank-1 reductions.
// grid (128, 2), block 128. y==0 -> product/g_pr_t/g_a, y==1 -> person/.../g_b
// g_a additionally absorbs the rank-0 term 2*ln2*sum(w2).
// ---------------------------------------------------------------------------
__global__ __launch_bounds__(NTHR) void proj_kernel(
    const float* __restrict__ product, const float* __restrict__ person,
    const float* __restrict__ w1, const float* __restrict__ w2) {
  __shared__ float rows[8][S_DIM];
  __shared__ float red[8][4];
  __shared__ float wpart[4];
  const int s = threadIdx.x;
  const int row0 = blockIdx.x * 8;
  const float* src; const float* wb;
  if (blockIdx.y == 0) { src = product; wb = w1; }
  else                 { src = person;  wb = w1 + S_DIM * S_DIM; }

#pragma unroll
  for (int r = 0; r < 8; ++r) rows[r][s] = src[(row0 + r) * S_DIM + s];

  const float wv = w2[s];
  {  // block-reduce sum(w2) into wpart
    float t = wv;
#pragma unroll
    for (int o = 16; o > 0; o >>= 1) t += __shfl_down_sync(0xffffffffu, t, o);
    if ((s & 31) == 0) wpart[s >> 5] = t;
  }
  __syncthreads();

  float acc[8] = {0.f, 0.f, 0.f, 0.f, 0.f, 0.f, 0.f, 0.f};
#pragma unroll 4
  for (int k = 0; k < S_DIM; ++k) {
    const float w = wb[k * S_DIM + s];  // coalesced over s
#pragma unroll
    for (int r = 0; r < 8; ++r) acc[r] = fmaf(rows[r][k], w, acc[r]);
  }

#pragma unroll
  for (int r = 0; r < 8; ++r) {
    if (blockIdx.y == 0) g_pr_t[s][row0 + r] = acc[r];
    else                 g_pe_t[s][row0 + r] = acc[r];
    float v = acc[r] * wv;
#pragma unroll
    for (int o = 16; o > 0; o >>= 1) v += __shfl_down_sync(0xffffffffu, v, o);
    if ((s & 31) == 0) red[r][s >> 5] = v;
  }
  __syncthreads();
  if (s < 8) {
    const float t = red[s][0] + red[s][1] + red[s][2] + red[s][3];
    if (blockIdx.y == 0) {
      const float W = wpart[0] + wpart[1] + wpart[2] + wpart[3];
      g_a[row0 + s] = t + 1.38629436f * W;  // + 2*ln2*sum(w2) (rank-0 term)
    } else {
      g_b[row0 + s] = t;
    }
  }
}

// One packed step: acc += w * (v/8 - v^2/192), v = (pr+pe)^2, coeffs pre-folded.
__device__ __forceinline__ uint64_t sp_step(uint64_t prd, uint64_t pe2,
                                            uint64_t cw1, uint64_t cw2,
                                            uint64_t acc) {
  const uint64_t z = addx2(prd, pe2);
  const uint64_t v = mulx2(z, z);
  const uint64_t u = fmax2(cw2, v, cw1);
  return fmax2(u, v, acc);
}

// Epilogue helper: finish one packed q-pair and stream 8 batches.
__device__ __forceinline__ void emit(uint64_t acc, float ap, float2 b2, int idx,
                                     const uint64_t* __restrict__ xv,
                                     uint64_t* __restrict__ ov) {
  const float2 g = unpk(acc);
  float m0 = fmaf(0.5f, ap + b2.x, g.x);
  float m1 = fmaf(0.5f, ap + b2.y, g.y);
  m0 = m0 >= 0.f ? m0 : 0.1f * m0;
  m1 = m1 >= 0.f ? m1 : 0.1f * m1;
  const uint64_t adj = pk(m0, m1);
  const int plane2 = (P_DIM * Q_DIM) >> 1;
#pragma unroll
  for (int b = 0; b < B_DIM; ++b) {
    const int o = b * plane2 + idx;
    ov[o] = mulx2(adj, xv[o]);
  }
}

// ---------------------------------------------------------------------------
// Main fused kernel. grid (32, 32) = 1024 CTAs, block 128, 8 CTAs/SM.
// s-reduction split into 2 phases of 64 to keep smem at 17KB (single wave).
// Micro-tile per thread: 2p x 2 packed q-pairs.
// softplus(z) = z/2 + ln2 + z^2/8 - z^4/192 + O(z^6); z/2 and ln2 terms are
// rank-1/rank-0 (in g_a/g_b), poly part accumulated here with folded w2.
// ---------------------------------------------------------------------------
__global__ __launch_bounds__(NTHR, 8) void adj_kernel(
    const float* __restrict__ x, const float* __restrict__ w2,
    float* __restrict__ out) {
  __shared__ float spr[SPH][TP];    // 8 KB
  __shared__ float spe[SPH][TQ];    // 8 KB
  __shared__ float4 scw[SPH];       // 1 KB: {w/8, w/8, -w/192, -w/192}

  const int tid = threadIdx.x;
  const int p0 = blockIdx.y * TP;
  const int q0 = blockIdx.x * TQ;

  const int qi = tid & 7;    // q pairs at q0 + 2*qi and q0 + 2*qi + 16
  const int pi = tid >> 3;   // p at p0 + 2*pi and p0 + 2*pi + 1
  const int qi2 = qi * 2, pi2 = pi * 2;

  uint64_t a00 = 0ull, a01 = 0ull, a10 = 0ull, a11 = 0ull;

#pragma unroll
  for (int ph = 0; ph < 2; ++ph) {
    const int s0 = ph * SPH;
    if (ph) __syncthreads();  // previous-phase tile fully consumed

    // Tile loads (float4 vectorized; sources transposed -> coalesced)
#pragma unroll
    for (int k = 0; k < (TP * SPH) / (NTHR * 4); ++k) {
      const int i = tid + k * NTHR;           // float4 index
      const int s = i >> 3, j = i & 7;        // 8 float4 per row
      *reinterpret_cast<float4*>(&spr[s][j * 4]) =
          *reinterpret_cast<const float4*>(&g_pr_t[s0 + s][p0 + j * 4]);
    }
#pragma unroll
    for (int k = 0; k < (TQ * SPH) / (NTHR * 4); ++k) {
      const int i = tid + k * NTHR;
      const int s = i >> 3, j = i & 7;
      *reinterpret_cast<float4*>(&spe[s][j * 4]) =
          *reinterpret_cast<const float4*>(&g_pe_t[s0 + s][q0 + j * 4]);
    }
    if (tid < SPH) {
      const float w = w2[s0 + tid];
      scw[tid] = make_float4(0.125f * w, 0.125f * w,
                             -5.2083333e-3f * w, -5.2083333e-3f * w);
    }
    __syncthreads();

#pragma unroll 4
    for (int s = 0; s < SPH; ++s) {
      const uint64_t peA = *reinterpret_cast<const uint64_t*>(&spe[s][qi2]);
      const uint64_t peB = *reinterpret_cast<const uint64_t*>(&spe[s][qi2 + 16]);
      const float2 pr = *reinterpret_cast<const float2*>(&spr[s][pi2]);
      const ulonglong2 cw = *reinterpret_cast<const ulonglong2*>(&scw[s]);
      const uint64_t prx = fdup(pr.x);
      const uint64_t pry = fdup(pr.y);
      a00 = sp_step(prx, peA, cw.x, cw.y, a00);
      a01 = sp_step(prx, peB, cw.x, cw.y, a01);
      a10 = sp_step(pry, peA, cw.x, cw.y, a10);
      a11 = sp_step(pry, peB, cw.x, cw.y, a11);
    }
  }

  // Epilogue: m = acc + 0.5*(a'_p + b_q); leaky relu; multiply into x.
  const float2 av = *reinterpret_cast<const float2*>(&g_a[p0 + pi2]);
  const float2 bA = *reinterpret_cast<const float2*>(&g_b[q0 + qi2]);
  const float2 bB = *reinterpret_cast<const float2*>(&g_b[q0 + qi2 + 16]);

  const uint64_t* xv = reinterpret_cast<const uint64_t*>(x);
  uint64_t* ov = reinterpret_cast<uint64_t*>(out);
  const int base = (((p0 + pi2) * Q_DIM + q0 + qi2) >> 1);  // float2 units

  emit(a00, av.x, bA, base,           xv, ov);
  emit(a01, av.x, bB, base + 8,       xv, ov);
  emit(a10, av.y, bA, base + 512,     xv, ov);
  emit(a11, av.y, bB, base + 512 + 8, xv, ov);
}

extern "C" void kernel_launch(void* const* d_in, const int* in_sizes, int n_in,
                              void* d_out, int out_size) {
  const float* x       = (const float*)d_in[0];  // [8,1024,1024]
  const float* product = (const float*)d_in[1];  // [1024,128]
  const float* person  = (const float*)d_in[2];  // [1024,128]
  const float* w1      = (const float*)d_in[3];  // [256,128]
  const float* w2      = (const float*)d_in[4];  // [128,1]
  float* out = (float*)d_out;                    // [8,1024,1024]

  proj_kernel<<<dim3(P_DIM / 8, 2), NTHR>>>(product, person, w1, w2);
  adj_kernel<<<dim3(Q_DIM / TQ, P_DIM / TP), NTHR>>>(x, w2, out);
}

// round 10
// speedup vs baseline: 1.0412x; 1.0412x over previous
#include <cuda_runtime.h>
#include <cstdint>

#define P_DIM 1024
#define Q_DIM 1024
#define S_DIM 128
#define B_DIM 8
#define KDIM  (3 * S_DIM)   // 384
#define KC    32            // K-chunk staged in smem
#define TM    64
#define TN    64

// Device-global scratch (allocation-free rule)
__device__ __align__(16) float g_A[P_DIM * KDIM];  // [p, 3s+j] tf32-rounded
__device__ __align__(16) float g_B[Q_DIM * KDIM];  // [q, 3s+j] tf32-rounded
__device__ __align__(16) float g_u[P_DIM];         // p-only terms (+ rank-0)
__device__ __align__(16) float g_t[Q_DIM];         // q-only terms

__device__ __forceinline__ float tf32r(float v) {
  uint32_t r;
  asm("cvt.rna.tf32.f32 %0, %1;" : "=r"(r) : "f"(v));
  return __uint_as_float(r);
}
__device__ __forceinline__ uint64_t mulx2(uint64_t a, uint64_t b) {
  uint64_t d; asm("mul.rn.f32x2 %0, %1, %2;" : "=l"(d) : "l"(a), "l"(b)); return d;
}
__device__ __forceinline__ uint64_t pk(float lo, float hi) {
  uint64_t r;
  asm("mov.b64 %0, {%1, %2};" : "=l"(r) : "r"(__float_as_uint(lo)), "r"(__float_as_uint(hi)));
  return r;
}

// ---------------------------------------------------------------------------
// Prologue. grid (128, 2), block 128; 8 rows/CTA.
// y==0: product side -> g_A rows + g_u.  y==1: person side -> g_B rows + g_t.
// softplus(z) ~= z/2 + ln2 + z^2/8 - z^4/192;  z = pr + pe.
// Cross terms (GEMM, K=3S):  A0=w(pr/4 - pr^3/48), A1=-w pr^2/32, A2=-w pr/48
//                            B0=pe, B1=pe^2, B2=pe^3
// u(p) = sum_s w(pr/2 + pr^2/8 - pr^4/192) + ln2*sum(w);  t(q) analogous.
// ---------------------------------------------------------------------------
__global__ __launch_bounds__(128) void proj_kernel(
    const float* __restrict__ product, const float* __restrict__ person,
    const float* __restrict__ w1, const float* __restrict__ w2) {
  __shared__ float rows[8][S_DIM];
  __shared__ float red[8][4];
  __shared__ float wpart[4];
  const int s = threadIdx.x;
  const int row0 = blockIdx.x * 8;
  const int side = blockIdx.y;
  const float* src = side ? person : product;
  const float* wb = side ? (w1 + S_DIM * S_DIM) : w1;

#pragma unroll
  for (int r = 0; r < 8; ++r) rows[r][s] = src[(row0 + r) * S_DIM + s];

  const float wv = w2[s];
  {
    float tsum = wv;
#pragma unroll
    for (int o = 16; o > 0; o >>= 1) tsum += __shfl_down_sync(0xffffffffu, tsum, o);
    if ((s & 31) == 0) wpart[s >> 5] = tsum;
  }
  __syncthreads();

  float acc[8] = {0.f, 0.f, 0.f, 0.f, 0.f, 0.f, 0.f, 0.f};
#pragma unroll 4
  for (int k = 0; k < S_DIM; ++k) {
    const float w = wb[k * S_DIM + s];
#pragma unroll
    for (int r = 0; r < 8; ++r) acc[r] = fmaf(rows[r][k], w, acc[r]);
  }

#pragma unroll
  for (int r = 0; r < 8; ++r) {
    const float v = acc[r];
    const float v2 = v * v, v3 = v2 * v, v4 = v2 * v2;
    float* dst = (side ? g_B : g_A) + (row0 + r) * KDIM + 3 * s;
    if (side == 0) {
      dst[0] = tf32r(wv * (0.25f * v - v3 * (1.f / 48.f)));
      dst[1] = tf32r(-wv * v2 * (1.f / 32.f));
      dst[2] = tf32r(-wv * v * (1.f / 48.f));
    } else {
      dst[0] = tf32r(v);
      dst[1] = tf32r(v2);
      dst[2] = tf32r(v3);
    }
    float rv = wv * (0.5f * v + 0.125f * v2 - v4 * (1.f / 192.f));
#pragma unroll
    for (int o = 16; o > 0; o >>= 1) rv += __shfl_down_sync(0xffffffffu, rv, o);
    if ((s & 31) == 0) red[r][s >> 5] = rv;
  }
  __syncthreads();
  if (s < 8) {
    float tt = red[s][0] + red[s][1] + red[s][2] + red[s][3];
    if (side == 0) {
      const float W = wpart[0] + wpart[1] + wpart[2] + wpart[3];
      g_u[row0 + s] = tt + 0.69314718f * W;  // fold rank-0 ln2*sum(w)
    } else {
      g_t[row0 + s] = tt;
    }
  }
}

// ---------------------------------------------------------------------------
// Fused GEMM (tf32 mma.sync) + epilogue.
// grid (16,16) = 256 CTAs, 128 threads (4 warps). CTA tile 64x64.
// Warp w computes rows [16w,16w+16) x all 64 cols via m16n8k8 frags.
// m = u_p + t_q + A.B^T; adj = leaky(m); out[b] = adj * x[b] (coalesced via
// smem re-permute of the m tile).
// ---------------------------------------------------------------------------
#define APAD 36   // row stride (floats) for A/B smem: conflict-free frag reads
#define MPAD 66   // row stride for m tile

__global__ __launch_bounds__(128) void adj2_kernel(
    const float* __restrict__ x, float* __restrict__ out) {
  __shared__ __align__(16) char smem_raw[2 * TM * APAD * 4];  // 18432 B
  float(*A_sm)[APAD] = reinterpret_cast<float(*)[APAD]>(smem_raw);
  float(*B_sm)[APAD] = reinterpret_cast<float(*)[APAD]>(smem_raw + TM * APAD * 4);
  float(*m_sm)[MPAD] = reinterpret_cast<float(*)[MPAD]>(smem_raw);  // reused after GEMM

  const int tid = threadIdx.x;
  const int warp = tid >> 5;
  const int lane = tid & 31;
  const int gid = lane >> 2;   // 0..7
  const int tig = lane & 3;    // 0..3
  const int p0 = blockIdx.y * TM;
  const int q0 = blockIdx.x * TN;

  float c[8][4];
#pragma unroll
  for (int i = 0; i < 8; ++i)
#pragma unroll
    for (int j = 0; j < 4; ++j) c[i][j] = 0.f;

  const int arow = warp * 16 + gid;

  for (int kc = 0; kc < KDIM; kc += KC) {
    if (kc) __syncthreads();
    // Cooperative chunk load: 64 rows x 32 K-floats each side, LDG.128.
#pragma unroll
    for (int j = 0; j < 4; ++j) {
      const int idx = tid + j * 128;          // 512 float4 total
      const int r = idx >> 3, c4 = (idx & 7) * 4;
      *reinterpret_cast<float4*>(&A_sm[r][c4]) =
          *reinterpret_cast<const float4*>(&g_A[(p0 + r) * KDIM + kc + c4]);
      *reinterpret_cast<float4*>(&B_sm[r][c4]) =
          *reinterpret_cast<const float4*>(&g_B[(q0 + r) * KDIM + kc + c4]);
    }
    __syncthreads();

#pragma unroll
    for (int ks = 0; ks < KC / 8; ++ks) {
      const int k0 = ks * 8;
      const uint32_t a0 = __float_as_uint(A_sm[arow][k0 + tig]);
      const uint32_t a1 = __float_as_uint(A_sm[arow + 8][k0 + tig]);
      const uint32_t a2 = __float_as_uint(A_sm[arow][k0 + tig + 4]);
      const uint32_t a3 = __float_as_uint(A_sm[arow + 8][k0 + tig + 4]);
#pragma unroll
      for (int nf = 0; nf < 8; ++nf) {
        const int n = nf * 8 + gid;
        const uint32_t b0 = __float_as_uint(B_sm[n][k0 + tig]);
        const uint32_t b1 = __float_as_uint(B_sm[n][k0 + tig + 4]);
        asm volatile(
            "mma.sync.aligned.m16n8k8.row.col.f32.tf32.tf32.f32 "
            "{%0,%1,%2,%3}, {%4,%5,%6,%7}, {%8,%9}, {%0,%1,%2,%3};"
            : "+f"(c[nf][0]), "+f"(c[nf][1]), "+f"(c[nf][2]), "+f"(c[nf][3])
            : "r"(a0), "r"(a1), "r"(a2), "r"(a3), "r"(b0), "r"(b1));
      }
    }
  }
  __syncthreads();  // all A/B smem reads done; region becomes m_sm

  // Fragment store: add rank-1 terms, leaky-relu, permute into m_sm.
  {
    const float u0 = g_u[p0 + arow];
    const float u1 = g_u[p0 + arow + 8];
#pragma unroll
    for (int nf = 0; nf < 8; ++nf) {
      const int col = nf * 8 + 2 * tig;
      const float2 tv = *reinterpret_cast<const float2*>(&g_t[q0 + col]);
      float m00 = c[nf][0] + u0 + tv.x;
      float m01 = c[nf][1] + u0 + tv.y;
      float m10 = c[nf][2] + u1 + tv.x;
      float m11 = c[nf][3] + u1 + tv.y;
      m00 = m00 >= 0.f ? m00 : 0.1f * m00;
      m01 = m01 >= 0.f ? m01 : 0.1f * m01;
      m10 = m10 >= 0.f ? m10 : 0.1f * m10;
      m11 = m11 >= 0.f ? m11 : 0.1f * m11;
      *reinterpret_cast<float2*>(&m_sm[arow][col]) = make_float2(m00, m01);
      *reinterpret_cast<float2*>(&m_sm[arow + 8][col]) = make_float2(m10, m11);
    }
  }
  __syncthreads();

  // Epilogue: coalesced stream over 8 batches.
  // Tile = 64 rows x 32 float2 = 2048 float2 -> 16 per thread.
  const uint64_t* xv = reinterpret_cast<const uint64_t*>(x);
  uint64_t* ov = reinterpret_cast<uint64_t*>(out);
  const int plane2 = (P_DIM * Q_DIM) >> 1;
#pragma unroll 4
  for (int i = 0; i < 16; ++i) {
    const int f = tid + i * 128;        // 0..2047
    const int row = f >> 5;             // 32 float2 per row -> row 0..63
    const int c2i = f & 31;
    const float2 av = *reinterpret_cast<const float2*>(&m_sm[row][c2i * 2]);
    const uint64_t adj = pk(av.x, av.y);
    const int g2 = (((p0 + row) << 10) + q0 + c2i * 2) >> 1;
#pragma unroll
    for (int b = 0; b < B_DIM; ++b) {
      const int o = b * plane2 + g2;
      ov[o] = mulx2(adj, xv[o]);
    }
  }
}

extern "C" void kernel_launch(void* const* d_in, const int* in_sizes, int n_in,
                              void* d_out, int out_size) {
  const float* x       = (const float*)d_in[0];  // [8,1024,1024]
  const float* product = (const float*)d_in[1];  // [1024,128]
  const float* person  = (const float*)d_in[2];  // [1024,128]
  const float* w1      = (const float*)d_in[3];  // [256,128]
  const float* w2      = (const float*)d_in[4];  // [128,1]
  float* out = (float*)d_out;                    // [8,1024,1024]

  proj_kernel<<<dim3(P_DIM / 8, 2), 128>>>(product, person, w1, w2);
  adj2_kernel<<<dim3(Q_DIM / TN, P_DIM / TM), 128>>>(x, out);
}

// round 11
// speedup vs baseline: 1.1063x; 1.0626x over previous
#include <cuda_runtime.h>
#include <cstdint>

#define P_DIM 1024
#define Q_DIM 1024
#define S_DIM 128
#define B_DIM 8
#define KDIM  (3 * S_DIM)   // 384
#define KC    32            // K-chunk staged in smem
#define TM    64
#define TN    64

// Device-global scratch (allocation-free rule)
__device__ __align__(16) float g_A[P_DIM * KDIM];  // [p, 3s+j] tf32-rounded
__device__ __align__(16) float g_B[Q_DIM * KDIM];  // [q, 3s+j] tf32-rounded
__device__ __align__(16) float g_u[P_DIM];         // p-only terms (+ rank-0)
__device__ __align__(16) float g_t[Q_DIM];         // q-only terms
__device__ __align__(16) float g_m[P_DIM * Q_DIM]; // leaky(m) adjacency (4MB)

__device__ __forceinline__ float tf32r(float v) {
  uint32_t r;
  asm("cvt.rna.tf32.f32 %0, %1;" : "=r"(r) : "f"(v));
  return __uint_as_float(r);
}

// ---------------------------------------------------------------------------
// Prologue. grid (128, 2), block 128; 8 rows/CTA.
// y==0: product side -> g_A rows + g_u.  y==1: person side -> g_B rows + g_t.
// softplus(z) ~= z/2 + ln2 + z^2/8 - z^4/192;  z = pr + pe.
// Cross terms (GEMM, K=3S):  A0=w(pr/4 - pr^3/48), A1=-w pr^2/32, A2=-w pr/48
//                            B0=pe, B1=pe^2, B2=pe^3
// u(p) = sum_s w(pr/2 + pr^2/8 - pr^4/192) + ln2*sum(w);  t(q) analogous.
// ---------------------------------------------------------------------------
__global__ __launch_bounds__(128) void proj_kernel(
    const float* __restrict__ product, const float* __restrict__ person,
    const float* __restrict__ w1, const float* __restrict__ w2) {
  __shared__ float rows[8][S_DIM];
  __shared__ float red[8][4];
  __shared__ float wpart[4];
  const int s = threadIdx.x;
  const int row0 = blockIdx.x * 8;
  const int side = blockIdx.y;
  const float* src = side ? person : product;
  const float* wb = side ? (w1 + S_DIM * S_DIM) : w1;

#pragma unroll
  for (int r = 0; r < 8; ++r) rows[r][s] = src[(row0 + r) * S_DIM + s];

  const float wv = w2[s];
  {
    float tsum = wv;
#pragma unroll
    for (int o = 16; o > 0; o >>= 1) tsum += __shfl_down_sync(0xffffffffu, tsum, o);
    if ((s & 31) == 0) wpart[s >> 5] = tsum;
  }
  __syncthreads();

  float acc[8] = {0.f, 0.f, 0.f, 0.f, 0.f, 0.f, 0.f, 0.f};
#pragma unroll 4
  for (int k = 0; k < S_DIM; ++k) {
    const float w = wb[k * S_DIM + s];
#pragma unroll
    for (int r = 0; r < 8; ++r) acc[r] = fmaf(rows[r][k], w, acc[r]);
  }

#pragma unroll
  for (int r = 0; r < 8; ++r) {
    const float v = acc[r];
    const float v2 = v * v, v3 = v2 * v, v4 = v2 * v2;
    float* dst = (side ? g_B : g_A) + (row0 + r) * KDIM + 3 * s;
    if (side == 0) {
      dst[0] = tf32r(wv * (0.25f * v - v3 * (1.f / 48.f)));
      dst[1] = tf32r(-wv * v2 * (1.f / 32.f));
      dst[2] = tf32r(-wv * v * (1.f / 48.f));
    } else {
      dst[0] = tf32r(v);
      dst[1] = tf32r(v2);
      dst[2] = tf32r(v3);
    }
    float rv = wv * (0.5f * v + 0.125f * v2 - v4 * (1.f / 192.f));
#pragma unroll
    for (int o = 16; o > 0; o >>= 1) rv += __shfl_down_sync(0xffffffffu, rv, o);
    if ((s & 31) == 0) red[r][s >> 5] = rv;
  }
  __syncthreads();
  if (s < 8) {
    float tt = red[s][0] + red[s][1] + red[s][2] + red[s][3];
    if (side == 0) {
      const float W = wpart[0] + wpart[1] + wpart[2] + wpart[3];
      g_u[row0 + s] = tt + 0.69314718f * W;  // fold rank-0 ln2*sum(w)
    } else {
      g_t[row0 + s] = tt;
    }
  }
}

// ---------------------------------------------------------------------------
// GEMM (tf32 mma.sync): m = leaky(u_p + t_q + A.B^T) -> g_m.
// grid (16,16) = 256 CTAs, 256 threads (8 warps). CTA tile 64x64.
// Warp w: rows [16*(w>>1), +16), cols [32*(w&1), +32) -> 4 n-frags.
// ---------------------------------------------------------------------------
#define APAD 36   // row stride (floats) for A/B smem: conflict-free frag reads

__global__ __launch_bounds__(256) void gemm_kernel() {
  __shared__ __align__(16) float A_sm[TM][APAD];
  __shared__ __align__(16) float B_sm[TN][APAD];

  const int tid = threadIdx.x;
  const int warp = tid >> 5;
  const int lane = tid & 31;
  const int gid = lane >> 2;   // 0..7
  const int tig = lane & 3;    // 0..3
  const int p0 = blockIdx.y * TM;
  const int q0 = blockIdx.x * TN;
  const int r0 = (warp >> 1) * 16;   // warp row base within tile
  const int c0 = (warp & 1) * 32;    // warp col base within tile

  float c[4][4];
#pragma unroll
  for (int i = 0; i < 4; ++i)
#pragma unroll
    for (int j = 0; j < 4; ++j) c[i][j] = 0.f;

  const int arow = r0 + gid;

  for (int kc = 0; kc < KDIM; kc += KC) {
    if (kc) __syncthreads();
    // Chunk load: 64 rows x 32 K-floats each side = 512 float4 per matrix.
#pragma unroll
    for (int j = 0; j < 2; ++j) {
      const int idx = tid + j * 256;          // 0..511
      const int r = idx >> 3, c4 = (idx & 7) * 4;
      *reinterpret_cast<float4*>(&A_sm[r][c4]) =
          *reinterpret_cast<const float4*>(&g_A[(p0 + r) * KDIM + kc + c4]);
      *reinterpret_cast<float4*>(&B_sm[r][c4]) =
          *reinterpret_cast<const float4*>(&g_B[(q0 + r) * KDIM + kc + c4]);
    }
    __syncthreads();

#pragma unroll
    for (int ks = 0; ks < KC / 8; ++ks) {
      const int k0 = ks * 8;
      const uint32_t a0 = __float_as_uint(A_sm[arow][k0 + tig]);
      const uint32_t a1 = __float_as_uint(A_sm[arow + 8][k0 + tig]);
      const uint32_t a2 = __float_as_uint(A_sm[arow][k0 + tig + 4]);
      const uint32_t a3 = __float_as_uint(A_sm[arow + 8][k0 + tig + 4]);
#pragma unroll
      for (int nf = 0; nf < 4; ++nf) {
        const int n = c0 + nf * 8 + gid;
        const uint32_t b0 = __float_as_uint(B_sm[n][k0 + tig]);
        const uint32_t b1 = __float_as_uint(B_sm[n][k0 + tig + 4]);
        asm volatile(
            "mma.sync.aligned.m16n8k8.row.col.f32.tf32.tf32.f32 "
            "{%0,%1,%2,%3}, {%4,%5,%6,%7}, {%8,%9}, {%0,%1,%2,%3};"
            : "+f"(c[nf][0]), "+f"(c[nf][1]), "+f"(c[nf][2]), "+f"(c[nf][3])
            : "r"(a0), "r"(a1), "r"(a2), "r"(a3), "r"(b0), "r"(b1));
      }
    }
  }

  // Epilogue: add rank-1 terms, leaky-relu, store m tile (float2, from regs).
  const float u0 = g_u[p0 + arow];
  const float u1 = g_u[p0 + arow + 8];
#pragma unroll
  for (int nf = 0; nf < 4; ++nf) {
    const int col = c0 + nf * 8 + 2 * tig;
    const float2 tv = *reinterpret_cast<const float2*>(&g_t[q0 + col]);
    float m00 = c[nf][0] + u0 + tv.x;
    float m01 = c[nf][1] + u0 + tv.y;
    float m10 = c[nf][2] + u1 + tv.x;
    float m11 = c[nf][3] + u1 + tv.y;
    m00 = m00 >= 0.f ? m00 : 0.1f * m00;
    m01 = m01 >= 0.f ? m01 : 0.1f * m01;
    m10 = m10 >= 0.f ? m10 : 0.1f * m10;
    m11 = m11 >= 0.f ? m11 : 0.1f * m11;
    *reinterpret_cast<float2*>(&g_m[(p0 + arow) * Q_DIM + q0 + col]) =
        make_float2(m00, m01);
    *reinterpret_cast<float2*>(&g_m[(p0 + arow + 8) * Q_DIM + q0 + col]) =
        make_float2(m10, m11);
  }
}

// ---------------------------------------------------------------------------
// Streaming multiply: out[b,p,q] = m[p,q] * x[b,p,q].
// grid 1024 CTAs x 256 threads; one float4 of m per thread, 8 batches.
// Full-chip parallelism (262144 threads), MLP=8, fully coalesced.
// ---------------------------------------------------------------------------
__global__ __launch_bounds__(256) void mul_kernel(
    const float* __restrict__ x, float* __restrict__ out) {
  const int idx = blockIdx.x * 256 + threadIdx.x;  // float4 index in plane
  const float4 a = reinterpret_cast<const float4*>(g_m)[idx];
  const float4* xv = reinterpret_cast<const float4*>(x);
  float4* ov = reinterpret_cast<float4*>(out);
  const int plane4 = (P_DIM * Q_DIM) >> 2;
#pragma unroll
  for (int b = 0; b < B_DIM; ++b) {
    float4 v = xv[b * plane4 + idx];
    v.x *= a.x; v.y *= a.y; v.z *= a.z; v.w *= a.w;
    ov[b * plane4 + idx] = v;
  }
}

extern "C" void kernel_launch(void* const* d_in, const int* in_sizes, int n_in,
                              void* d_out, int out_size) {
  const float* x       = (const float*)d_in[0];  // [8,1024,1024]
  const float* product = (const float*)d_in[1];  // [1024,128]
  const float* person  = (const float*)d_in[2];  // [1024,128]
  const float* w1      = (const float*)d_in[3];  // [256,128]
  const float* w2      = (const float*)d_in[4];  // [128,1]
  float* out = (float*)d_out;                    // [8,1024,1024]

  proj_kernel<<<dim3(P_DIM / 8, 2), 128>>>(product, person, w1, w2);
  gemm_kernel<<<dim3(Q_DIM / TN, P_DIM / TM), 256>>>();
  mul_kernel<<<(P_DIM * Q_DIM / 4) / 256, 256>>>(x, out);
}